// round 13
// baseline (speedup 1.0000x reference)
#include <cuda_runtime.h>
#include <cuda_bf16.h>
#include <math.h>
#include <stdint.h>

// ---------------- constants ----------------
#define HH    64
#define WW    192
#define HW    12288        // 64*192
#define WP    194
#define PP    12804        // 66*194
#define CIN   256
#define COUT  128
#define NTILE 96           // HW / 128 pixel tiles

// ---------------- scratch ----------------
__device__ float          g_xpad[CIN * PP];
__device__ __nv_bfloat16  g_y1s[2][HW * CIN];    // gather out, pixel-major [p][k], 2 bf16 splits
__device__ __nv_bfloat16  g_dws[2][HW * COUT];   // depthwise out, pixel-major [p][k], 2 splits
__device__ float          g_bufP[COUT * HW];     // GEMM out (pre-BN), channel-major
__device__ float          g_ss[3 * COUT * 2];    // fused (scale, shift) per stage
__device__ float2         g_part[COUT * NTILE];  // BN partials from GEMM epilogue
__device__ __nv_bfloat16  g_wredS[2][COUT * CIN];
__device__ __nv_bfloat16  g_pw1S[2][COUT * COUT];
__device__ __nv_bfloat16  g_pw2S[2][COUT * COUT];

// ---------------- helpers ----------------
__device__ __forceinline__ uint32_t smem_u32(const void* p) {
    uint32_t a;
    asm("{ .reg .u64 t; cvta.to.shared.u64 t, %1; cvt.u32.u64 %0, t; }" : "=r"(a) : "l"(p));
    return a;
}
__device__ __forceinline__ uint32_t sw128(uint32_t b) { return b ^ ((b >> 3) & 0x70); }

// 2-way bf16 split: v = b0 + b1 + O(2^-17 v)
__device__ __forceinline__ void split2(float v, ushort& o0, ushort& o1) {
    __nv_bfloat16 b0 = __float2bfloat16(v);
    float r = v - __bfloat162float(b0);
    o0 = __bfloat16_as_ushort(b0);
    o1 = __bfloat16_as_ushort(__float2bfloat16(r));
}

// ---------------- weight split prep ----------------
__global__ __launch_bounds__(256) void wprep_kernel(const float* __restrict__ wred,
                                                    const float* __restrict__ pw1,
                                                    const float* __restrict__ pw2) {
    int t = blockIdx.x * 256 + threadIdx.x;   // 65536 total
    ushort a, b;
    if (t < COUT * CIN) {
        split2(wred[t], a, b);
        g_wredS[0][t] = __ushort_as_bfloat16(a);
        g_wredS[1][t] = __ushort_as_bfloat16(b);
    } else if (t < COUT * CIN + COUT * COUT) {
        int i = t - COUT * CIN;
        split2(pw1[i], a, b);
        g_pw1S[0][i] = __ushort_as_bfloat16(a);
        g_pw1S[1][i] = __ushort_as_bfloat16(b);
    } else {
        int i = t - COUT * CIN - COUT * COUT;
        split2(pw2[i], a, b);
        g_pw2S[0][i] = __ushort_as_bfloat16(a);
        g_pw2S[1][i] = __ushort_as_bfloat16(b);
    }
}

// ---------------- pad ----------------
__global__ __launch_bounds__(256) void pad_kernel(const float* __restrict__ x) {
    int t = blockIdx.x * 256 + threadIdx.x;
    int c = t / PP;
    int r = (t % PP) / WP;
    int col = t % WP;
    float v = 0.0f;
    if (r >= 1 && r <= HH && col >= 1 && col <= WW)
        v = x[(c * HH + (r - 1)) * WW + (col - 1)];
    g_xpad[t] = v;
}

// ---------------- deformable gather -> bf16x2 pixel-major ----------------
__global__ __launch_bounds__(192) void gather_kernel(const float* __restrict__ xr,
                                                     const float* __restrict__ rout) {
    const int i = blockIdx.x;
    const int cg = blockIdx.y;
    const int j = threadIdx.x;

    const int TT[6] = {0, 2, 3, 5, 6, 8};
    const int XO[6] = {-1, 1, -1, 1, -1, 1};
    const int YO[6] = {-1, -1, 0, 0, 1, 1};

    float w[6][4];
    int   id[6][4];
    {
        float xv = xr[i * WW + j];
        float sig = 1.0f / (1.0f + expf(-xv));
        float o = __fmul_rn(3.0f, sig);
        float v = (float)((i + 1) * WP + (j + 1));
        #pragma unroll
        for (int tt = 0; tt < 6; tt++) {
            float fxo = (float)XO[tt];
            float fyW = (float)(YO[tt] * WP);
            float offv  = __fadd_rn(__fmul_rn(o, fxo), fyW);
            float pre   = __fadd_rn(__fadd_rn(v, fxo), fyW);
            float after = __fadd_rn(pre, offv);
            float avf  = fminf(fmaxf(__fadd_rn(pre, floorf(offv)), 0.0f), (float)(PP - 1));
            float avf1 = fminf(fmaxf(__fadd_rn(avf, fxo), 0.0f), (float)(PP - 1));
            float avc  = fminf(fmaxf(__fadd_rn(pre, ceilf(offv)), 0.0f), (float)(PP - 1));
            float avc1 = fminf(fmaxf(__fadd_rn(avc, fxo), 0.0f), (float)(PP - 1));
            float a  = fabsf(__fadd_rn(after, -avf));
            float b  = fabsf(__fadd_rn(avf1, -after));
            float cc = fabsf(__fadd_rn(after, -avc1));
            float d  = fabsf(__fadd_rn(avc, -after));
            float A1 = fabsf(__fdiv_rn(__fadd_rn(after, -avf), (float)WP));
            float A2 = fabsf(__fdiv_rn(__fadd_rn(avc1, -after), (float)WP));
            w[tt][0] = A1 * a;  id[tt][0] = (int)avf;
            w[tt][1] = A1 * b;  id[tt][1] = (int)avf1;
            w[tt][2] = A2 * cc; id[tt][2] = (int)avc1;
            w[tt][3] = A2 * d;  id[tt][3] = (int)avc;
        }
    }

    const int p = i * WW + j;
    const int c0 = cg * 32;

    uint4 pk[2][4];                    // 2 splits x 32 ushorts
    ushort* up = (ushort*)pk;

    for (int cc = 0; cc < 32; cc++) {
        int c = c0 + cc;
        const float* xp = g_xpad + c * PP;
        float acc = 0.0f;
        #pragma unroll
        for (int tt = 0; tt < 6; tt++) {
            float tv = w[tt][0] * __ldg(xp + id[tt][0])
                     + w[tt][1] * __ldg(xp + id[tt][1])
                     + w[tt][2] * __ldg(xp + id[tt][2])
                     + w[tt][3] * __ldg(xp + id[tt][3]);
            acc = fmaf(__ldg(rout + c * 9 + TT[tt]), tv, acc);
        }
        split2(acc, up[0 * 32 + cc], up[1 * 32 + cc]);
    }

    #pragma unroll
    for (int s = 0; s < 2; s++) {
        uint4* dst = (uint4*)(&g_y1s[s][(size_t)p * CIN + c0]);
        dst[0] = pk[s][0]; dst[1] = pk[s][1]; dst[2] = pk[s][2]; dst[3] = pk[s][3];
    }
}

// ---------------- bf16 split GEMM on mma.sync (HMMA path) ----------------
// D[128 ch][128 px] per CTA; 8 warps (4 m x 2 n), warp tile 32x64.
// 3 product passes: a0*b0, a0*b1, a1*b0  (a1*b1 ~ 2^-16, dropped).
// SMEM: A0,A1,B0,B1 tiles 128x64 bf16 (16KB each, SW128 swizzle) + 2KB partials.
#define GSM_SIZE (65536 + 2048)

template <int K>
__global__ __launch_bounds__(256, 1) void mma_gemm_kernel(int asel) {
    extern __shared__ char smem[];
    float2* spart = (float2*)(smem + 65536);
    const uint32_t sb = smem_u32(smem);
    const int tid = threadIdx.x;
    const int wid = tid >> 5, lane = tid & 31;
    const int warp_m = wid & 3, warp_n = wid >> 2;
    const int p0 = blockIdx.x * 128;

    const __nv_bfloat16* Ap[2];
    const __nv_bfloat16* Bp[2];
    #pragma unroll
    for (int s = 0; s < 2; s++) {
        Ap[s] = (asel == 0) ? g_wredS[s] : (asel == 1) ? g_pw1S[s] : g_pw2S[s];
        Bp[s] = (K == 256) ? g_y1s[s] : g_dws[s];
    }

    float acc[2][8][4];
    #pragma unroll
    for (int mt = 0; mt < 2; mt++)
        #pragma unroll
        for (int nt = 0; nt < 8; nt++)
            #pragma unroll
            for (int r = 0; r < 4; r++) acc[mt][nt][r] = 0.0f;

    for (int k0 = 0; k0 < K; k0 += 64) {
        // load 4 tiles (A0,A1,B0,B1), each 128 rows x 64 bf16 (128B rows)
        #pragma unroll
        for (int s = 0; s < 2; s++) {
            #pragma unroll
            for (int it = 0; it < 4; it++) {
                int idx = it * 256 + tid;              // 1024 16B chunks per tile
                int row = idx >> 3, kg = idx & 7;
                uint32_t so = sw128(row * 128 + kg * 16);
                *(uint4*)(smem + s * 16384 + so) =
                    *(const uint4*)(Ap[s] + row * K + k0 + kg * 8);
                *(uint4*)(smem + 32768 + s * 16384 + so) =
                    *(const uint4*)(Bp[s] + (size_t)(p0 + row) * K + k0 + kg * 8);
            }
        }
        __syncthreads();

        #pragma unroll
        for (int pass = 0; pass < 3; pass++) {
            const uint32_t abase = sb + ((pass == 2) ? 16384 : 0);
            const uint32_t bbase = sb + 32768 + ((pass == 1) ? 16384 : 0);
            #pragma unroll
            for (int ks = 0; ks < 4; ks++) {
                const int koff2 = (ks * 16 + ((lane >> 4) << 3)) * 2;  // byte offset in row
                uint32_t a[2][4], b[8][2];
                #pragma unroll
                for (int mt = 0; mt < 2; mt++) {
                    int row = warp_m * 32 + mt * 16 + (lane & 15);
                    uint32_t ad = abase + sw128(row * 128 + koff2);
                    asm volatile("ldmatrix.sync.aligned.m8n8.x4.shared.b16 {%0,%1,%2,%3}, [%4];"
                        : "=r"(a[mt][0]), "=r"(a[mt][1]), "=r"(a[mt][2]), "=r"(a[mt][3])
                        : "r"(ad));
                }
                #pragma unroll
                for (int np = 0; np < 4; np++) {
                    int row = warp_n * 64 + np * 16 + (lane & 15);
                    uint32_t ad = bbase + sw128(row * 128 + koff2);
                    uint32_t r0, r1, r2, r3;
                    asm volatile("ldmatrix.sync.aligned.m8n8.x4.shared.b16 {%0,%1,%2,%3}, [%4];"
                        : "=r"(r0), "=r"(r1), "=r"(r2), "=r"(r3) : "r"(ad));
                    b[np * 2][0] = r0;     b[np * 2][1] = r2;
                    b[np * 2 + 1][0] = r1; b[np * 2 + 1][1] = r3;
                }
                #pragma unroll
                for (int mt = 0; mt < 2; mt++)
                    #pragma unroll
                    for (int nt = 0; nt < 8; nt++)
                        asm volatile(
                            "mma.sync.aligned.m16n8k16.row.col.f32.bf16.bf16.f32 "
                            "{%0,%1,%2,%3}, {%4,%5,%6,%7}, {%8,%9}, {%0,%1,%2,%3};"
                            : "+f"(acc[mt][nt][0]), "+f"(acc[mt][nt][1]),
                              "+f"(acc[mt][nt][2]), "+f"(acc[mt][nt][3])
                            : "r"(a[mt][0]), "r"(a[mt][1]), "r"(a[mt][2]), "r"(a[mt][3]),
                              "r"(b[nt][0]), "r"(b[nt][1]));
            }
        }
        __syncthreads();
    }

    // epilogue: write channel-major fp32 + fused BN partials
    const int r0 = lane >> 2, cpair = (lane & 3) * 2;
    #pragma unroll
    for (int mt = 0; mt < 2; mt++) {
        #pragma unroll
        for (int h = 0; h < 2; h++) {
            const int ch = warp_m * 32 + mt * 16 + h * 8 + r0;
            float s = 0.0f, q = 0.0f;
            float* op = g_bufP + (size_t)ch * HW + p0 + warp_n * 64;
            #pragma unroll
            for (int nt = 0; nt < 8; nt++) {
                float v0 = acc[mt][nt][h * 2], v1 = acc[mt][nt][h * 2 + 1];
                s += v0 + v1;
                q = fmaf(v0, v0, q); q = fmaf(v1, v1, q);
                *(float2*)(op + nt * 8 + cpair) = make_float2(v0, v1);
            }
            s += __shfl_xor_sync(0xffffffffu, s, 1); q += __shfl_xor_sync(0xffffffffu, q, 1);
            s += __shfl_xor_sync(0xffffffffu, s, 2); q += __shfl_xor_sync(0xffffffffu, q, 2);
            if ((lane & 3) == 0) spart[warp_n * 128 + ch] = make_float2(s, q);
        }
    }
    __syncthreads();
    if (tid < 128) {
        float2 pa = spart[tid], pb = spart[128 + tid];
        g_part[tid * NTILE + blockIdx.x] = make_float2(pa.x + pb.x, pa.y + pb.y);
    }
}

// ---------------- BN finalize ----------------
__global__ __launch_bounds__(128) void bn_fin_kernel(const float* __restrict__ gamma,
                                                     const float* __restrict__ beta,
                                                     int stage) {
    const int c = threadIdx.x;
    float s = 0.0f, q = 0.0f;
    #pragma unroll 8
    for (int i = 0; i < NTILE; i++) {
        float2 p = g_part[c * NTILE + i];
        s += p.x; q += p.y;
    }
    float mu = s / (float)HW;
    float var = q / (float)HW - mu * mu;
    float sc = gamma[c] * rsqrtf(var + 1e-5f);
    g_ss[stage * 2 * COUT + c * 2]     = sc;
    g_ss[stage * 2 * COUT + c * 2 + 1] = beta[c] - mu * sc;
}

// ---------------- depthwise 3x3 (BN+leaky fused on input) -> bf16x2 pixel-major ----------------
// grid (6, 64, 4), block 256: tile = 32 pixels x 32 channels
__global__ __launch_bounds__(256) void dw_kernel(const float* __restrict__ wdw, int stage) {
    __shared__ ushort tsm[2][32][36];
    const int jt = blockIdx.x, i = blockIdx.y, cg = blockIdx.z;
    const int tid = threadIdx.x, lane = tid & 31, wid = tid >> 5;
    const int j = jt * 32 + lane;

    #pragma unroll
    for (int rep = 0; rep < 4; rep++) {
        const int cl = rep * 8 + wid;
        const int c = cg * 32 + cl;
        const float sc = g_ss[stage * 2 * COUT + c * 2];
        const float sh = g_ss[stage * 2 * COUT + c * 2 + 1];
        const float* zp = g_bufP + (size_t)c * HW;
        float acc = 0.0f;
        #pragma unroll
        for (int di = 0; di < 3; di++) {
            int ii = i + di - 1;
            if ((unsigned)ii >= (unsigned)HH) continue;
            #pragma unroll
            for (int dj = 0; dj < 3; dj++) {
                int jj = j + dj - 1;
                if ((unsigned)jj >= (unsigned)WW) continue;
                float v = fmaf(zp[ii * WW + jj], sc, sh);
                v = (v >= 0.0f) ? v : 0.01f * v;
                acc = fmaf(__ldg(wdw + c * 9 + di * 3 + dj), v, acc);
            }
        }
        split2(acc, tsm[0][lane][cl], tsm[1][lane][cl]);
    }
    __syncthreads();

    const int pl = tid >> 3, cp = tid & 7;
    const int pix = i * WW + jt * 32 + pl;
    #pragma unroll
    for (int s = 0; s < 2; s++) {
        ushort4 v = *(ushort4*)&tsm[s][pl][cp * 4];
        *(ushort4*)(&g_dws[s][(size_t)pix * COUT + cg * 32 + cp * 4]) = v;
    }
}

// ---------------- final BN+LeakyReLU -> d_out ----------------
__global__ __launch_bounds__(256) void final_act_kernel(float* __restrict__ out) {
    const int c = blockIdx.y;
    const int t = blockIdx.x * 256 + threadIdx.x;
    const float sc = g_ss[2 * 2 * COUT + c * 2];
    const float sh = g_ss[2 * 2 * COUT + c * 2 + 1];
    float v = fmaf(g_bufP[(size_t)c * HW + t], sc, sh);
    v = (v >= 0.0f) ? v : 0.01f * v;
    out[(size_t)c * HW + t] = v;
}

// ---------------- launch ----------------
extern "C" void kernel_launch(void* const* d_in, const int* in_sizes, int n_in,
                              void* d_out, int out_size) {
    const float* x    = (const float*)d_in[0];
    const float* xr   = (const float*)d_in[1];
    const float* rout = (const float*)d_in[2];
    const float* wred = (const float*)d_in[3];
    const float* g_r  = (const float*)d_in[4];
    const float* b_r  = (const float*)d_in[5];
    const float* dw1  = (const float*)d_in[6];
    const float* pw1  = (const float*)d_in[7];
    const float* g1   = (const float*)d_in[8];
    const float* b1   = (const float*)d_in[9];
    const float* dw2  = (const float*)d_in[10];
    const float* pw2  = (const float*)d_in[11];
    const float* g2   = (const float*)d_in[12];
    const float* b2   = (const float*)d_in[13];
    float* out = (float*)d_out;

    cudaFuncSetAttribute(mma_gemm_kernel<256>, cudaFuncAttributeMaxDynamicSharedMemorySize, GSM_SIZE);
    cudaFuncSetAttribute(mma_gemm_kernel<128>, cudaFuncAttributeMaxDynamicSharedMemorySize, GSM_SIZE);

    wprep_kernel<<<256, 256>>>(wred, pw1, pw2);
    pad_kernel<<<(CIN * PP) / 256, 256>>>(x);
    gather_kernel<<<dim3(HH, 8), 192>>>(xr, rout);

    mma_gemm_kernel<256><<<NTILE, 256, GSM_SIZE>>>(0);
    bn_fin_kernel<<<1, 128>>>(g_r, b_r, 0);

    dw_kernel<<<dim3(6, HH, 4), 256>>>(dw1, 0);
    mma_gemm_kernel<128><<<NTILE, 256, GSM_SIZE>>>(1);
    bn_fin_kernel<<<1, 128>>>(g1, b1, 1);

    dw_kernel<<<dim3(6, HH, 4), 256>>>(dw2, 1);
    mma_gemm_kernel<128><<<NTILE, 256, GSM_SIZE>>>(2);
    bn_fin_kernel<<<1, 128>>>(g2, b2, 2);

    final_act_kernel<<<dim3(HW / 256, COUT), 256>>>(out);
}